// round 2
// baseline (speedup 1.0000x reference)
#include <cuda_runtime.h>
#include <cuda_bf16.h>
#include <math.h>

// Problem constants
#define BSZ 256
#define SEQ 64
#define HID 512
#define H2  1024
#define H4  2048
#define H8  4096
#define VOC 32000

// ---------------------------------------------------------------------------
// Scratch (no allocations allowed -> __device__ globals)
// ---------------------------------------------------------------------------
__device__ float g_seq   [SEQ * BSZ * HID];   // embedded sequence, (S*B, H) flat
__device__ float g_gxf   [SEQ * BSZ * H4];    // input proj, forward cell
__device__ float g_gxb   [SEQ * BSZ * H4];    // input proj, backward cell (natural order)
__device__ float g_gxc   [SEQ * BSZ * H8];    // input proj, combiner cell
__device__ float g_comb  [SEQ * BSZ * H2];    // concat(hf, hb) per step
__device__ float g_gates_f[BSZ * H4];
__device__ float g_gates_b[BSZ * H4];
__device__ float g_gates_c[BSZ * H8];
__device__ float g_hf[BSZ * HID];
__device__ float g_cf[BSZ * HID];
__device__ float g_hb[BSZ * HID];
__device__ float g_cb[BSZ * HID];
__device__ float g_hc[BSZ * H2];
__device__ float g_cc[BSZ * H2];

// ---------------------------------------------------------------------------
// Embedding gather: seq[i*H + h] = (idx==0) ? 0 : W_emb[idx*H + h]
// raw reshape (B,S,H)->(S,B,H) is a no-op on the flat buffer.
// ---------------------------------------------------------------------------
__global__ void embed_kernel(const int* __restrict__ x,
                             const float* __restrict__ W,
                             float* __restrict__ seq)
{
    int i = blockIdx.x * blockDim.x + threadIdx.x;   // over B*S*H = 8.4M
    if (i >= BSZ * SEQ * HID) return;
    int row = i / HID;
    int h   = i - row * HID;
    int idx = x[row];
    seq[i] = (idx == 0) ? 0.0f : W[(size_t)idx * HID + h];
}

// ---------------------------------------------------------------------------
// Generic tiled SGEMM:  C = A(MxK) * W(NxK)^T  [+ D] [+ bias0[n]] [+ bias1[n]]
// Requires M%64==0, N%64==0, K%16==0 (true for all shapes here).
// Two parameter sets, selected by blockIdx.z (fuses the f/b cells).
// ---------------------------------------------------------------------------
struct GemmSet {
    const float* A;
    const float* W;
    const float* D;      // optional additive input (same shape as C), may be null
    const float* bias0;  // optional per-column bias, may be null
    const float* bias1;  // optional per-column bias, may be null
    float*       C;
};

#define BM 64
#define BN 64
#define BK 16

__global__ __launch_bounds__(256)
void gemm_tn(GemmSet s0, GemmSet s1, int M, int N, int K)
{
    GemmSet s = (blockIdx.z == 0) ? s0 : s1;

    __shared__ __align__(16) float As[BK][BM + 4];
    __shared__ __align__(16) float Ws[BK][BN + 4];

    const int tid = threadIdx.x;          // 256 threads
    const int tx  = tid & 15;             // 0..15 -> N
    const int ty  = tid >> 4;             // 0..15 -> M
    const int n0  = blockIdx.x * BN;
    const int m0  = blockIdx.y * BM;

    const int lr = tid >> 2;              // 0..63  row within tile
    const int lq = tid & 3;               // 0..3   float4 within K-slab

    float acc[4][4];
#pragma unroll
    for (int i = 0; i < 4; ++i)
#pragma unroll
        for (int j = 0; j < 4; ++j) acc[i][j] = 0.0f;

    for (int kt = 0; kt < K; kt += BK) {
        // load A tile (64 rows x 16 K) -> As[k][m]
        {
            const float4 av = *reinterpret_cast<const float4*>(
                s.A + (size_t)(m0 + lr) * K + kt + lq * 4);
            As[lq * 4 + 0][lr] = av.x;
            As[lq * 4 + 1][lr] = av.y;
            As[lq * 4 + 2][lr] = av.z;
            As[lq * 4 + 3][lr] = av.w;
        }
        // load W tile (64 rows x 16 K) -> Ws[k][n]
        {
            const float4 wv = *reinterpret_cast<const float4*>(
                s.W + (size_t)(n0 + lr) * K + kt + lq * 4);
            Ws[lq * 4 + 0][lr] = wv.x;
            Ws[lq * 4 + 1][lr] = wv.y;
            Ws[lq * 4 + 2][lr] = wv.z;
            Ws[lq * 4 + 3][lr] = wv.w;
        }
        __syncthreads();

#pragma unroll
        for (int k = 0; k < BK; ++k) {
            const float4 a = *reinterpret_cast<const float4*>(&As[k][ty * 4]);
            const float4 b = *reinterpret_cast<const float4*>(&Ws[k][tx * 4]);
            float ar[4] = {a.x, a.y, a.z, a.w};
            float br[4] = {b.x, b.y, b.z, b.w};
#pragma unroll
            for (int i = 0; i < 4; ++i)
#pragma unroll
                for (int j = 0; j < 4; ++j)
                    acc[i][j] = fmaf(ar[i], br[j], acc[i][j]);
        }
        __syncthreads();
    }

    // epilogue
#pragma unroll
    for (int i = 0; i < 4; ++i) {
        const int m = m0 + ty * 4 + i;
        const size_t row = (size_t)m * N + n0 + tx * 4;
#pragma unroll
        for (int j = 0; j < 4; ++j) {
            const int n = n0 + tx * 4 + j;
            float v = acc[i][j];
            if (s.D)     v += s.D[row + j];
            if (s.bias0) v += s.bias0[n];
            if (s.bias1) v += s.bias1[n];
            s.C[row + j] = v;
        }
    }
}

// ---------------------------------------------------------------------------
// LSTM pointwise gate update. gates G is (B, 4*Hd), chunks [i, f, g, o].
// Updates h, c in place; optionally scatters h into 'out' with row stride.
// Two parameter sets selected by blockIdx.z (fuses f/b cells).
// ---------------------------------------------------------------------------
struct PWSet {
    const float* G;
    float* h;
    float* c;
    float* out;     // may be null
    int Hd;
    int ostride;
    int total;      // B * Hd
};

__device__ __forceinline__ float sigmoidf(float v) {
    return 1.0f / (1.0f + expf(-v));
}

__global__ __launch_bounds__(256)
void lstm_pw(PWSet s0, PWSet s1)
{
    PWSet s = (blockIdx.z == 0) ? s0 : s1;
    int idx = blockIdx.x * blockDim.x + threadIdx.x;
    if (idx >= s.total) return;
    int b = idx / s.Hd;
    int j = idx - b * s.Hd;
    const float* g = s.G + (size_t)b * 4 * s.Hd;

    float ig = sigmoidf(g[j]);
    float fg = sigmoidf(g[s.Hd + j]);
    float gg = tanhf(g[2 * s.Hd + j]);
    float og = sigmoidf(g[3 * s.Hd + j]);

    float c2 = fg * s.c[idx] + ig * gg;
    float h2 = og * tanhf(c2);
    s.c[idx] = c2;
    s.h[idx] = h2;
    if (s.out) s.out[(size_t)b * s.ostride + j] = h2;
}

// ---------------------------------------------------------------------------
// kernel_launch
// ---------------------------------------------------------------------------
extern "C" void kernel_launch(void* const* d_in, const int* in_sizes, int n_in,
                              void* d_out, int out_size)
{
    const int*   x     = (const int*)  d_in[0];
    const float* W_emb = (const float*)d_in[1];
    const float* Wih_f = (const float*)d_in[2];
    const float* Whh_f = (const float*)d_in[3];
    const float* bih_f = (const float*)d_in[4];
    const float* bhh_f = (const float*)d_in[5];
    const float* Wih_b = (const float*)d_in[6];
    const float* Whh_b = (const float*)d_in[7];
    const float* bih_b = (const float*)d_in[8];
    const float* bhh_b = (const float*)d_in[9];
    const float* Wih_c = (const float*)d_in[10];
    const float* Whh_c = (const float*)d_in[11];
    const float* bih_c = (const float*)d_in[12];
    const float* bhh_c = (const float*)d_in[13];
    const float* Wout  = (const float*)d_in[14];
    const float* bout  = (const float*)d_in[15];
    const float* h0f   = (const float*)d_in[16];
    const float* c0f   = (const float*)d_in[17];
    const float* h0b   = (const float*)d_in[18];
    const float* c0b   = (const float*)d_in[19];
    const float* h0c   = (const float*)d_in[20];
    const float* c0c   = (const float*)d_in[21];
    float* out = (float*)d_out;

    float *seq, *gxf, *gxb, *gxc, *comb, *gates_f, *gates_b, *gates_c;
    float *hf, *cf, *hb, *cb, *hc, *cc;
    cudaGetSymbolAddress((void**)&seq,     g_seq);
    cudaGetSymbolAddress((void**)&gxf,     g_gxf);
    cudaGetSymbolAddress((void**)&gxb,     g_gxb);
    cudaGetSymbolAddress((void**)&gxc,     g_gxc);
    cudaGetSymbolAddress((void**)&comb,    g_comb);
    cudaGetSymbolAddress((void**)&gates_f, g_gates_f);
    cudaGetSymbolAddress((void**)&gates_b, g_gates_b);
    cudaGetSymbolAddress((void**)&gates_c, g_gates_c);
    cudaGetSymbolAddress((void**)&hf, g_hf);
    cudaGetSymbolAddress((void**)&cf, g_cf);
    cudaGetSymbolAddress((void**)&hb, g_hb);
    cudaGetSymbolAddress((void**)&cb, g_cb);
    cudaGetSymbolAddress((void**)&hc, g_hc);
    cudaGetSymbolAddress((void**)&cc, g_cc);

    // initial states
    cudaMemcpyAsync(hf, h0f, BSZ * HID * sizeof(float), cudaMemcpyDeviceToDevice, 0);
    cudaMemcpyAsync(cf, c0f, BSZ * HID * sizeof(float), cudaMemcpyDeviceToDevice, 0);
    cudaMemcpyAsync(hb, h0b, BSZ * HID * sizeof(float), cudaMemcpyDeviceToDevice, 0);
    cudaMemcpyAsync(cb, c0b, BSZ * HID * sizeof(float), cudaMemcpyDeviceToDevice, 0);
    cudaMemcpyAsync(hc, h0c, BSZ * H2  * sizeof(float), cudaMemcpyDeviceToDevice, 0);
    cudaMemcpyAsync(cc, c0c, BSZ * H2  * sizeof(float), cudaMemcpyDeviceToDevice, 0);

    // embedding gather (raw reshape -> flat)
    {
        int total = BSZ * SEQ * HID;
        embed_kernel<<<(total + 255) / 256, 256>>>(x, W_emb, seq);
    }

    // Batched input projections for f and b cells:
    //   gx[t*B+b] = seq[t*B+b] @ Wih^T + (bih + bhh)
    {
        GemmSet sf{seq, Wih_f, nullptr, bih_f, bhh_f, gxf};
        GemmSet sb{seq, Wih_b, nullptr, bih_b, bhh_b, gxb};
        dim3 grid(H4 / BN, (SEQ * BSZ) / BM, 2);
        gemm_tn<<<grid, 256>>>(sf, sb, SEQ * BSZ, H4, HID);
    }

    // f/b recurrences (b consumes input projections in reversed order)
    for (int t = 0; t < SEQ; ++t) {
        GemmSet rf{hf, Whh_f, gxf + (size_t)t        * BSZ * H4, nullptr, nullptr, gates_f};
        GemmSet rb{hb, Whh_b, gxb + (size_t)(SEQ-1-t)* BSZ * H4, nullptr, nullptr, gates_b};
        dim3 grid(H4 / BN, BSZ / BM, 2);
        gemm_tn<<<grid, 256>>>(rf, rb, BSZ, H4, HID);

        PWSet pf{gates_f, hf, cf, comb + (size_t)t * BSZ * H2,        HID, H2, BSZ * HID};
        PWSet pb{gates_b, hb, cb, comb + (size_t)t * BSZ * H2 + HID,  HID, H2, BSZ * HID};
        dim3 pgrid((BSZ * HID + 255) / 256, 1, 2);
        lstm_pw<<<pgrid, 256>>>(pf, pb);
    }

    // Batched input projection for combiner cell
    {
        GemmSet sc{comb, Wih_c, nullptr, bih_c, bhh_c, gxc};
        dim3 grid(H8 / BN, (SEQ * BSZ) / BM, 1);
        gemm_tn<<<grid, 256>>>(sc, sc, SEQ * BSZ, H8, H2);
    }

    // combiner recurrence (only final h needed)
    for (int t = 0; t < SEQ; ++t) {
        GemmSet rc{hc, Whh_c, gxc + (size_t)t * BSZ * H8, nullptr, nullptr, gates_c};
        dim3 grid(H8 / BN, BSZ / BM, 1);
        gemm_tn<<<grid, 256>>>(rc, rc, BSZ, H8, H2);

        PWSet pc{gates_c, hc, cc, nullptr, H2, 0, BSZ * H2};
        dim3 pgrid((BSZ * H2 + 255) / 256, 1, 1);
        lstm_pw<<<pgrid, 256>>>(pc, pc);
    }

    // output head: out = hc @ Wout^T + bout
    {
        GemmSet so{hc, Wout, nullptr, bout, nullptr, out};
        dim3 grid(VOC / BN, BSZ / BM, 1);
        gemm_tn<<<grid, 256>>>(so, so, BSZ, VOC, H2);
    }
}

// round 3
// speedup vs baseline: 2.1138x; 2.1138x over previous
#include <cuda_runtime.h>
#include <cuda_bf16.h>
#include <math.h>

// Problem constants
#define BSZ 256
#define SEQ 64
#define HID 512
#define H2  1024
#define H4  2048
#define H8  4096
#define VOC 32000

// ---------------------------------------------------------------------------
// Scratch (no allocations allowed -> __device__ globals)
// ---------------------------------------------------------------------------
__device__ float g_seq   [SEQ * BSZ * HID];
__device__ float g_gxf   [SEQ * BSZ * H4];
__device__ float g_gxb   [SEQ * BSZ * H4];
__device__ float g_gxc   [SEQ * BSZ * H8];
__device__ float g_comb  [SEQ * BSZ * H2];
__device__ float g_gates_f[BSZ * H4];
__device__ float g_gates_b[BSZ * H4];
__device__ float g_gates_c[BSZ * H8];
__device__ float g_hf[BSZ * HID];
__device__ float g_cf[BSZ * HID];
__device__ float g_hb[BSZ * HID];
__device__ float g_cb[BSZ * HID];
__device__ float g_hc[BSZ * H2];
__device__ float g_cc[BSZ * H2];

// ---------------------------------------------------------------------------
// Embedding gather, float4-vectorized.
// ---------------------------------------------------------------------------
__global__ __launch_bounds__(256)
void embed_kernel(const int* __restrict__ x,
                  const float* __restrict__ W,
                  float4* __restrict__ seq)
{
    const int H4v = HID / 4;
    int i = blockIdx.x * blockDim.x + threadIdx.x;   // over B*S*H/4
    if (i >= BSZ * SEQ * H4v) return;
    int row = i / H4v;
    int h4  = i - row * H4v;
    int idx = x[row];
    float4 v = make_float4(0.f, 0.f, 0.f, 0.f);
    if (idx != 0)
        v = reinterpret_cast<const float4*>(W)[(size_t)idx * H4v + h4];
    seq[i] = v;
}

// ---------------------------------------------------------------------------
// tf32 tensor-core GEMM:  C = A(MxK) * W(NxK)^T [+ D] [+ b0[n]] [+ b1[n]]
// Block tile 64x128, BK=16, 4 warps (warp tile 32x64), double-buffered smem.
// Requires M%64==0, N%128==0, K%16==0 (true for all shapes here).
// Two parameter sets selected by blockIdx.z (fuses f/b cells).
// ---------------------------------------------------------------------------
struct GemmSet {
    const float* A;
    const float* W;
    const float* D;
    const float* b0;
    const float* b1;
    float*       C;
};

#define BM 64
#define BN 128
#define BK 16
#define AST 72     // BM + 8 pad -> conflict-free fragment LDS
#define BST 136    // BN + 8 pad

__device__ __forceinline__ unsigned f2tf(float f) {
    unsigned r;
    asm("cvt.rna.tf32.f32 %0, %1;" : "=r"(r) : "f"(f));
    return r;
}

__global__ __launch_bounds__(128)
void gemm_tf32(GemmSet s0, GemmSet s1, int M, int N, int K)
{
    GemmSet s = blockIdx.z ? s1 : s0;

    __shared__ unsigned As[2][BK][AST];   // [k][m]
    __shared__ unsigned Bs[2][BK][BST];   // [k][n]

    const int tid  = threadIdx.x;
    const int lane = tid & 31;
    const int wid  = tid >> 5;
    const int wm   = wid & 1;             // warp m position (0..1)
    const int wn   = wid >> 1;            // warp n position (0..1)
    const int n0   = blockIdx.x * BN;
    const int m0   = blockIdx.y * BM;
    const int T    = K / BK;

    float4 aReg[2], bReg[4];

    // Loader mapping: contiguous lanes -> contiguous tile rows (conflict-free
    // transpose STS; gmem gathers are row-strided float4s, mostly L2 hits).
    auto ldg_tile = [&](int kt) {
#pragma unroll
        for (int p = 0; p < 2; ++p) {
            int idx = tid + 128 * p;             // 0..255
            int q = idx >> 6, row = idx & 63;
            aReg[p] = *reinterpret_cast<const float4*>(
                s.A + (size_t)(m0 + row) * K + kt * BK + q * 4);
        }
#pragma unroll
        for (int p = 0; p < 4; ++p) {
            int idx = tid + 128 * p;             // 0..511
            int q = idx >> 7, row = idx & 127;
            bReg[p] = *reinterpret_cast<const float4*>(
                s.W + (size_t)(n0 + row) * K + kt * BK + q * 4);
        }
    };
    auto sts_tile = [&](int buf) {
#pragma unroll
        for (int p = 0; p < 2; ++p) {
            int idx = tid + 128 * p;
            int q = idx >> 6, row = idx & 63;
            As[buf][q * 4 + 0][row] = f2tf(aReg[p].x);
            As[buf][q * 4 + 1][row] = f2tf(aReg[p].y);
            As[buf][q * 4 + 2][row] = f2tf(aReg[p].z);
            As[buf][q * 4 + 3][row] = f2tf(aReg[p].w);
        }
#pragma unroll
        for (int p = 0; p < 4; ++p) {
            int idx = tid + 128 * p;
            int q = idx >> 7, row = idx & 127;
            Bs[buf][q * 4 + 0][row] = f2tf(bReg[p].x);
            Bs[buf][q * 4 + 1][row] = f2tf(bReg[p].y);
            Bs[buf][q * 4 + 2][row] = f2tf(bReg[p].z);
            Bs[buf][q * 4 + 3][row] = f2tf(bReg[p].w);
        }
    };

    float acc[2][8][4];
#pragma unroll
    for (int i = 0; i < 2; ++i)
#pragma unroll
        for (int j = 0; j < 8; ++j)
#pragma unroll
            for (int r = 0; r < 4; ++r) acc[i][j][r] = 0.f;

    ldg_tile(0);
    sts_tile(0);
    __syncthreads();

    for (int kt = 0; kt < T; ++kt) {
        if (kt + 1 < T) ldg_tile(kt + 1);
        const int buf = kt & 1;
#pragma unroll
        for (int ks = 0; ks < 2; ++ks) {
            const int c = ks * 8 + (lane & 3);       // k index of fragment
            unsigned a[2][4];
#pragma unroll
            for (int mt = 0; mt < 2; ++mt) {
                int r = wm * 32 + mt * 16 + (lane >> 2);
                a[mt][0] = As[buf][c    ][r];
                a[mt][1] = As[buf][c    ][r + 8];
                a[mt][2] = As[buf][c + 4][r];
                a[mt][3] = As[buf][c + 4][r + 8];
            }
#pragma unroll
            for (int nt = 0; nt < 8; ++nt) {
                int n = wn * 64 + nt * 8 + (lane >> 2);
                unsigned b0 = Bs[buf][c    ][n];
                unsigned b1 = Bs[buf][c + 4][n];
#pragma unroll
                for (int mt = 0; mt < 2; ++mt) {
                    asm volatile(
                        "mma.sync.aligned.m16n8k8.row.col.f32.tf32.tf32.f32 "
                        "{%0,%1,%2,%3}, {%4,%5,%6,%7}, {%8,%9}, {%0,%1,%2,%3};"
                        : "+f"(acc[mt][nt][0]), "+f"(acc[mt][nt][1]),
                          "+f"(acc[mt][nt][2]), "+f"(acc[mt][nt][3])
                        : "r"(a[mt][0]), "r"(a[mt][1]),
                          "r"(a[mt][2]), "r"(a[mt][3]),
                          "r"(b0), "r"(b1));
                }
            }
        }
        if (kt + 1 < T) {
            sts_tile((kt + 1) & 1);
            __syncthreads();
        }
    }

    // Epilogue: c0/c1 -> (row, n/n+1), c2/c3 -> (row+8, n/n+1)
#pragma unroll
    for (int mt = 0; mt < 2; ++mt) {
#pragma unroll
        for (int nt = 0; nt < 8; ++nt) {
            int m = m0 + wm * 32 + mt * 16 + (lane >> 2);
            int n = n0 + wn * 64 + nt * 8 + (lane & 3) * 2;
#pragma unroll
            for (int rr = 0; rr < 2; ++rr) {
                int mm = m + rr * 8;
                size_t off = (size_t)mm * N + n;
                float v0 = acc[mt][nt][rr * 2 + 0];
                float v1 = acc[mt][nt][rr * 2 + 1];
                if (s.D)  { v0 += s.D[off];  v1 += s.D[off + 1]; }
                if (s.b0) { v0 += s.b0[n];   v1 += s.b0[n + 1]; }
                if (s.b1) { v0 += s.b1[n];   v1 += s.b1[n + 1]; }
                *reinterpret_cast<float2*>(s.C + off) = make_float2(v0, v1);
            }
        }
    }
}

// ---------------------------------------------------------------------------
// LSTM pointwise gate update, float4-vectorized.
// ---------------------------------------------------------------------------
struct PWSet {
    const float* G;
    float* h;
    float* c;
    float* out;     // may be null
    int Hd;
    int ostride;
    int total;      // B * Hd
};

__device__ __forceinline__ float sigf(float v) {
    return 1.0f / (1.0f + __expf(-v));
}
__device__ __forceinline__ float lstm1(float gi, float gf, float gg, float go,
                                       float c, float& cn) {
    cn = sigf(gf) * c + sigf(gi) * tanhf(gg);
    return sigf(go) * tanhf(cn);
}

__global__ __launch_bounds__(256)
void lstm_pw(PWSet s0, PWSet s1)
{
    PWSet s = blockIdx.z ? s1 : s0;
    int i4 = blockIdx.x * blockDim.x + threadIdx.x;
    int total4 = s.total >> 2;
    if (i4 >= total4) return;
    int Hd4 = s.Hd >> 2;
    int b  = i4 / Hd4;
    int j4 = i4 - b * Hd4;

    const float4* G4 = reinterpret_cast<const float4*>(s.G + (size_t)b * 4 * s.Hd);
    float4 gi = G4[j4];
    float4 gf = G4[Hd4 + j4];
    float4 gg = G4[2 * Hd4 + j4];
    float4 go = G4[3 * Hd4 + j4];
    float4 cv = reinterpret_cast<const float4*>(s.c)[i4];

    float4 cn, hn;
    hn.x = lstm1(gi.x, gf.x, gg.x, go.x, cv.x, cn.x);
    hn.y = lstm1(gi.y, gf.y, gg.y, go.y, cv.y, cn.y);
    hn.z = lstm1(gi.z, gf.z, gg.z, go.z, cv.z, cn.z);
    hn.w = lstm1(gi.w, gf.w, gg.w, go.w, cv.w, cn.w);

    reinterpret_cast<float4*>(s.c)[i4] = cn;
    reinterpret_cast<float4*>(s.h)[i4] = hn;
    if (s.out)
        *reinterpret_cast<float4*>(s.out + (size_t)b * s.ostride + j4 * 4) = hn;
}

// ---------------------------------------------------------------------------
// kernel_launch
// ---------------------------------------------------------------------------
extern "C" void kernel_launch(void* const* d_in, const int* in_sizes, int n_in,
                              void* d_out, int out_size)
{
    const int*   x     = (const int*)  d_in[0];
    const float* W_emb = (const float*)d_in[1];
    const float* Wih_f = (const float*)d_in[2];
    const float* Whh_f = (const float*)d_in[3];
    const float* bih_f = (const float*)d_in[4];
    const float* bhh_f = (const float*)d_in[5];
    const float* Wih_b = (const float*)d_in[6];
    const float* Whh_b = (const float*)d_in[7];
    const float* bih_b = (const float*)d_in[8];
    const float* bhh_b = (const float*)d_in[9];
    const float* Wih_c = (const float*)d_in[10];
    const float* Whh_c = (const float*)d_in[11];
    const float* bih_c = (const float*)d_in[12];
    const float* bhh_c = (const float*)d_in[13];
    const float* Wout  = (const float*)d_in[14];
    const float* bout  = (const float*)d_in[15];
    const float* h0f   = (const float*)d_in[16];
    const float* c0f   = (const float*)d_in[17];
    const float* h0b   = (const float*)d_in[18];
    const float* c0b   = (const float*)d_in[19];
    const float* h0c   = (const float*)d_in[20];
    const float* c0c   = (const float*)d_in[21];
    float* out = (float*)d_out;

    float *seq, *gxf, *gxb, *gxc, *comb, *gates_f, *gates_b, *gates_c;
    float *hf, *cf, *hb, *cb, *hc, *cc;
    cudaGetSymbolAddress((void**)&seq,     g_seq);
    cudaGetSymbolAddress((void**)&gxf,     g_gxf);
    cudaGetSymbolAddress((void**)&gxb,     g_gxb);
    cudaGetSymbolAddress((void**)&gxc,     g_gxc);
    cudaGetSymbolAddress((void**)&comb,    g_comb);
    cudaGetSymbolAddress((void**)&gates_f, g_gates_f);
    cudaGetSymbolAddress((void**)&gates_b, g_gates_b);
    cudaGetSymbolAddress((void**)&gates_c, g_gates_c);
    cudaGetSymbolAddress((void**)&hf, g_hf);
    cudaGetSymbolAddress((void**)&cf, g_cf);
    cudaGetSymbolAddress((void**)&hb, g_hb);
    cudaGetSymbolAddress((void**)&cb, g_cb);
    cudaGetSymbolAddress((void**)&hc, g_hc);
    cudaGetSymbolAddress((void**)&cc, g_cc);

    // initial states
    cudaMemcpyAsync(hf, h0f, BSZ * HID * sizeof(float), cudaMemcpyDeviceToDevice, 0);
    cudaMemcpyAsync(cf, c0f, BSZ * HID * sizeof(float), cudaMemcpyDeviceToDevice, 0);
    cudaMemcpyAsync(hb, h0b, BSZ * HID * sizeof(float), cudaMemcpyDeviceToDevice, 0);
    cudaMemcpyAsync(cb, c0b, BSZ * HID * sizeof(float), cudaMemcpyDeviceToDevice, 0);
    cudaMemcpyAsync(hc, h0c, BSZ * H2  * sizeof(float), cudaMemcpyDeviceToDevice, 0);
    cudaMemcpyAsync(cc, c0c, BSZ * H2  * sizeof(float), cudaMemcpyDeviceToDevice, 0);

    // embedding gather (raw reshape -> flat)
    {
        int total4 = BSZ * SEQ * (HID / 4);
        embed_kernel<<<(total4 + 255) / 256, 256>>>(
            x, W_emb, (float4*)seq);
    }

    // Batched input projections for f and b cells
    {
        GemmSet sf{seq, Wih_f, nullptr, bih_f, bhh_f, gxf};
        GemmSet sb{seq, Wih_b, nullptr, bih_b, bhh_b, gxb};
        dim3 grid(H4 / BN, (SEQ * BSZ) / BM, 2);
        gemm_tf32<<<grid, 128>>>(sf, sb, SEQ * BSZ, H4, HID);
    }

    // f/b recurrences (b consumes input projections in reversed order)
    for (int t = 0; t < SEQ; ++t) {
        GemmSet rf{hf, Whh_f, gxf + (size_t)t          * BSZ * H4, nullptr, nullptr, gates_f};
        GemmSet rb{hb, Whh_b, gxb + (size_t)(SEQ-1-t)  * BSZ * H4, nullptr, nullptr, gates_b};
        dim3 grid(H4 / BN, BSZ / BM, 2);
        gemm_tf32<<<grid, 128>>>(rf, rb, BSZ, H4, HID);

        PWSet pf{gates_f, hf, cf, comb + (size_t)t * BSZ * H2,        HID, H2, BSZ * HID};
        PWSet pb{gates_b, hb, cb, comb + (size_t)t * BSZ * H2 + HID,  HID, H2, BSZ * HID};
        dim3 pgrid((BSZ * HID / 4 + 255) / 256, 1, 2);
        lstm_pw<<<pgrid, 256>>>(pf, pb);
    }

    // Batched input projection for combiner cell
    {
        GemmSet sc{comb, Wih_c, nullptr, bih_c, bhh_c, gxc};
        dim3 grid(H8 / BN, (SEQ * BSZ) / BM, 1);
        gemm_tf32<<<grid, 128>>>(sc, sc, SEQ * BSZ, H8, H2);
    }

    // combiner recurrence (only final h needed)
    for (int t = 0; t < SEQ; ++t) {
        GemmSet rc{hc, Whh_c, gxc + (size_t)t * BSZ * H8, nullptr, nullptr, gates_c};
        dim3 grid(H8 / BN, BSZ / BM, 1);
        gemm_tf32<<<grid, 128>>>(rc, rc, BSZ, H8, H2);

        PWSet pc{gates_c, hc, cc, nullptr, H2, 0, BSZ * H2};
        dim3 pgrid((BSZ * H2 / 4 + 255) / 256, 1, 1);
        lstm_pw<<<pgrid, 256>>>(pc, pc);
    }

    // output head: out = hc @ Wout^T + bout
    {
        GemmSet so{hc, Wout, nullptr, bout, nullptr, out};
        dim3 grid(VOC / BN, BSZ / BM, 1);
        gemm_tf32<<<grid, 128>>>(so, so, BSZ, VOC, H2);
    }
}

// round 4
// speedup vs baseline: 3.6716x; 1.7370x over previous
#include <cuda_runtime.h>
#include <cuda_bf16.h>
#include <math.h>

// Problem constants
#define BSZ 256
#define SEQ 64
#define HID 512
#define H2  1024
#define H4  2048
#define H8  4096
#define VOC 32000

// ---------------------------------------------------------------------------
// Scratch (no allocations allowed -> __device__ globals)
// ---------------------------------------------------------------------------
__device__ float g_seq   [SEQ * BSZ * HID];
__device__ float g_gxf   [SEQ * BSZ * H4];
__device__ float g_gxb   [SEQ * BSZ * H4];
__device__ float g_gxc   [SEQ * BSZ * H8];
__device__ float g_comb  [SEQ * BSZ * H2];
__device__ float g_hf[2][BSZ * HID];
__device__ float g_cf[BSZ * HID];
__device__ float g_hb[2][BSZ * HID];
__device__ float g_cb[BSZ * HID];
__device__ float g_hc[2][BSZ * H2];
__device__ float g_cc[BSZ * H2];

// ---------------------------------------------------------------------------
// Embedding gather, float4-vectorized.
// ---------------------------------------------------------------------------
__global__ __launch_bounds__(256)
void embed_kernel(const int* __restrict__ x,
                  const float* __restrict__ W,
                  float4* __restrict__ seq)
{
    const int H4v = HID / 4;
    int i = blockIdx.x * blockDim.x + threadIdx.x;
    if (i >= BSZ * SEQ * H4v) return;
    int row = i / H4v;
    int h4  = i - row * H4v;
    int idx = x[row];
    float4 v = make_float4(0.f, 0.f, 0.f, 0.f);
    if (idx != 0)
        v = reinterpret_cast<const float4*>(W)[(size_t)idx * H4v + h4];
    seq[i] = v;
}

// ---------------------------------------------------------------------------
// tf32 tensor-core GEMM, 64x128 block tile, BK=16, 256 threads (8 warps,
// warp tile 32x32), double-buffered smem in [row][k] layout (stride 20:
// conflict-free fragment LDS, vectorized STS.128 on load path).
//
// Plain mode  (FUSED=false): C = A(MxK) @ W(NxK)^T [+D] [+b0] [+b1]
// Fused mode  (FUSED=true):  gate-interleaved column mapping; each block
//   covers 32 j-columns x 4 gates; epilogue applies the LSTM cell:
//     pre = acc + gx[m][gate*Hd+j]
//     c'  = sig(pre_f)*c + sig(pre_i)*tanh(pre_g);  h' = sig(pre_o)*tanh(c')
//   writing c (in place), hout, and optionally comb.
// ---------------------------------------------------------------------------
struct GemmSet {
    const float* A;
    const float* W;
    const float* D;      // plain: optional addend (MxN); fused: gx (B,4*Hd)
    const float* b0;     // plain only
    const float* b1;     // plain only
    float*       C;      // plain only
    float*       cbuf;   // fused: cell state (B,Hd), read+write
    float*       hout;   // fused: next h (B,Hd)
    float*       comb;   // fused: optional (B, combStride) h scatter
    int          combStride;
};

#define BM 64
#define BN 128
#define BKK 16
#define KST 20    // smem k-stride (16 + 4 pad): banks (20r+c)%32 distinct

__device__ __forceinline__ unsigned f2tf(float f) {
    unsigned r;
    asm("cvt.rna.tf32.f32 %0, %1;" : "=r"(r) : "f"(f));
    return r;
}
__device__ __forceinline__ float sigf(float v) {
    return 1.0f / (1.0f + __expf(-v));
}

template<bool FUSED>
__global__ __launch_bounds__(256)
void gemm_tf32(GemmSet s0, GemmSet s1, int M, int N, int K, int Hd)
{
    GemmSet s = blockIdx.z ? s1 : s0;

    __shared__ unsigned As[2][BM][KST];
    __shared__ unsigned Bs[2][BN][KST];

    const int tid  = threadIdx.x;
    const int lane = tid & 31;
    const int wid  = tid >> 5;
    const int wm   = wid & 1;       // 0..1 -> m offset wm*32
    const int wn   = wid >> 1;      // 0..3 -> n offset wn*32
    const int m0   = blockIdx.y * BM;
    const int n0   = blockIdx.x * BN;   // plain column base
    const int n0j  = blockIdx.x * 32;   // fused j base
    const int T    = K / BKK;

    float4 aR;
    float4 bR[2];

    // A loader: 64 rows x 16 k = 256 float4; thread -> row=tid>>2, k4=tid&3
    const int a_row = tid >> 2;
    const int a_k4  = tid & 3;
    // B loader: 128 rows x 16 k = 512 float4; 2 iters
    int b_row[2], b_k4[2];
    const float* b_src[2];
#pragma unroll
    for (int p = 0; p < 2; ++p) {
        int idx = tid + 256 * p;
        int row = idx >> 2;
        b_row[p] = row;
        b_k4[p]  = idx & 3;
        int wrow;
        if (FUSED) {
            int wn_r = row >> 5;
            int t    = row & 31;
            int gate = t >> 3;
            int cc   = t & 7;
            int j    = n0j + wn_r * 8 + cc;
            wrow = gate * Hd + j;
        } else {
            wrow = n0 + row;
        }
        b_src[p] = s.W + (size_t)wrow * K;
    }

    auto ldg_tile = [&](int kt) {
        aR = *reinterpret_cast<const float4*>(
            s.A + (size_t)(m0 + a_row) * K + kt * BKK + a_k4 * 4);
#pragma unroll
        for (int p = 0; p < 2; ++p)
            bR[p] = *reinterpret_cast<const float4*>(
                b_src[p] + kt * BKK + b_k4[p] * 4);
    };
    auto sts_tile = [&](int buf) {
        unsigned* ap = &As[buf][a_row][a_k4 * 4];
        ap[0] = f2tf(aR.x); ap[1] = f2tf(aR.y);
        ap[2] = f2tf(aR.z); ap[3] = f2tf(aR.w);
#pragma unroll
        for (int p = 0; p < 2; ++p) {
            unsigned* bp = &Bs[buf][b_row[p]][b_k4[p] * 4];
            bp[0] = f2tf(bR[p].x); bp[1] = f2tf(bR[p].y);
            bp[2] = f2tf(bR[p].z); bp[3] = f2tf(bR[p].w);
        }
    };

    float acc[2][4][4];
#pragma unroll
    for (int i = 0; i < 2; ++i)
#pragma unroll
        for (int j = 0; j < 4; ++j)
#pragma unroll
            for (int r = 0; r < 4; ++r) acc[i][j][r] = 0.f;

    ldg_tile(0);
    sts_tile(0);
    __syncthreads();

    for (int kt = 0; kt < T; ++kt) {
        if (kt + 1 < T) ldg_tile(kt + 1);
        const int buf = kt & 1;
#pragma unroll
        for (int ks = 0; ks < 2; ++ks) {
            const int c = ks * 8 + (lane & 3);
            unsigned a[2][4];
#pragma unroll
            for (int mt = 0; mt < 2; ++mt) {
                int r = wm * 32 + mt * 16 + (lane >> 2);
                a[mt][0] = As[buf][r    ][c];
                a[mt][1] = As[buf][r + 8][c];
                a[mt][2] = As[buf][r    ][c + 4];
                a[mt][3] = As[buf][r + 8][c + 4];
            }
#pragma unroll
            for (int nt = 0; nt < 4; ++nt) {
                int n = wn * 32 + nt * 8 + (lane >> 2);
                unsigned b0 = Bs[buf][n][c];
                unsigned b1 = Bs[buf][n][c + 4];
#pragma unroll
                for (int mt = 0; mt < 2; ++mt) {
                    asm volatile(
                        "mma.sync.aligned.m16n8k8.row.col.f32.tf32.tf32.f32 "
                        "{%0,%1,%2,%3}, {%4,%5,%6,%7}, {%8,%9}, {%0,%1,%2,%3};"
                        : "+f"(acc[mt][nt][0]), "+f"(acc[mt][nt][1]),
                          "+f"(acc[mt][nt][2]), "+f"(acc[mt][nt][3])
                        : "r"(a[mt][0]), "r"(a[mt][1]),
                          "r"(a[mt][2]), "r"(a[mt][3]),
                          "r"(b0), "r"(b1));
                }
            }
        }
        if (kt + 1 < T) {
            sts_tile((kt + 1) & 1);
            __syncthreads();
        }
    }

    if (!FUSED) {
        // Plain epilogue: acc[mt][nt][rr*2+cc] -> C[m + rr*8][n + cc]
#pragma unroll
        for (int mt = 0; mt < 2; ++mt) {
#pragma unroll
            for (int nt = 0; nt < 4; ++nt) {
                int m = m0 + wm * 32 + mt * 16 + (lane >> 2);
                int n = n0 + wn * 32 + nt * 8 + (lane & 3) * 2;
#pragma unroll
                for (int rr = 0; rr < 2; ++rr) {
                    int mm = m + rr * 8;
                    size_t off = (size_t)mm * N + n;
                    float v0 = acc[mt][nt][rr * 2 + 0];
                    float v1 = acc[mt][nt][rr * 2 + 1];
                    if (s.D)  { v0 += s.D[off];  v1 += s.D[off + 1]; }
                    if (s.b0) { v0 += s.b0[n];   v1 += s.b0[n + 1]; }
                    if (s.b1) { v0 += s.b1[n];   v1 += s.b1[n + 1]; }
                    *reinterpret_cast<float2*>(s.C + off) = make_float2(v0, v1);
                }
            }
        }
    } else {
        // Fused LSTM epilogue: nt == gate (i,f,g,o); j pair per thread.
        const int j = n0j + wn * 8 + (lane & 3) * 2;
#pragma unroll
        for (int mt = 0; mt < 2; ++mt) {
#pragma unroll
            for (int rr = 0; rr < 2; ++rr) {
                int m = m0 + wm * 32 + mt * 16 + (lane >> 2) + rr * 8;
                const float* gx = s.D + (size_t)m * 4 * Hd;
                float2 di = *reinterpret_cast<const float2*>(gx +           j);
                float2 df = *reinterpret_cast<const float2*>(gx +     Hd +  j);
                float2 dg = *reinterpret_cast<const float2*>(gx + 2 * Hd +  j);
                float2 do_= *reinterpret_cast<const float2*>(gx + 3 * Hd +  j);
                float2 cv = *reinterpret_cast<const float2*>(
                    s.cbuf + (size_t)m * Hd + j);

                float pi0 = acc[mt][0][rr * 2 + 0] + di.x;
                float pi1 = acc[mt][0][rr * 2 + 1] + di.y;
                float pf0 = acc[mt][1][rr * 2 + 0] + df.x;
                float pf1 = acc[mt][1][rr * 2 + 1] + df.y;
                float pg0 = acc[mt][2][rr * 2 + 0] + dg.x;
                float pg1 = acc[mt][2][rr * 2 + 1] + dg.y;
                float po0 = acc[mt][3][rr * 2 + 0] + do_.x;
                float po1 = acc[mt][3][rr * 2 + 1] + do_.y;

                float cn0 = sigf(pf0) * cv.x + sigf(pi0) * tanhf(pg0);
                float cn1 = sigf(pf1) * cv.y + sigf(pi1) * tanhf(pg1);
                float hn0 = sigf(po0) * tanhf(cn0);
                float hn1 = sigf(po1) * tanhf(cn1);

                *reinterpret_cast<float2*>(s.cbuf + (size_t)m * Hd + j) =
                    make_float2(cn0, cn1);
                *reinterpret_cast<float2*>(s.hout + (size_t)m * Hd + j) =
                    make_float2(hn0, hn1);
                if (s.comb)
                    *reinterpret_cast<float2*>(
                        s.comb + (size_t)m * s.combStride + j) =
                        make_float2(hn0, hn1);
            }
        }
    }
}

// ---------------------------------------------------------------------------
// kernel_launch
// ---------------------------------------------------------------------------
extern "C" void kernel_launch(void* const* d_in, const int* in_sizes, int n_in,
                              void* d_out, int out_size)
{
    const int*   x     = (const int*)  d_in[0];
    const float* W_emb = (const float*)d_in[1];
    const float* Wih_f = (const float*)d_in[2];
    const float* Whh_f = (const float*)d_in[3];
    const float* bih_f = (const float*)d_in[4];
    const float* bhh_f = (const float*)d_in[5];
    const float* Wih_b = (const float*)d_in[6];
    const float* Whh_b = (const float*)d_in[7];
    const float* bih_b = (const float*)d_in[8];
    const float* bhh_b = (const float*)d_in[9];
    const float* Wih_c = (const float*)d_in[10];
    const float* Whh_c = (const float*)d_in[11];
    const float* bih_c = (const float*)d_in[12];
    const float* bhh_c = (const float*)d_in[13];
    const float* Wout  = (const float*)d_in[14];
    const float* bout  = (const float*)d_in[15];
    const float* h0f   = (const float*)d_in[16];
    const float* c0f   = (const float*)d_in[17];
    const float* h0b   = (const float*)d_in[18];
    const float* c0b   = (const float*)d_in[19];
    const float* h0c   = (const float*)d_in[20];
    const float* c0c   = (const float*)d_in[21];
    float* out = (float*)d_out;

    float *seq, *gxf, *gxb, *gxc, *comb;
    float *hf, *cf, *hb, *cb, *hc, *cc;
    cudaGetSymbolAddress((void**)&seq,  g_seq);
    cudaGetSymbolAddress((void**)&gxf,  g_gxf);
    cudaGetSymbolAddress((void**)&gxb,  g_gxb);
    cudaGetSymbolAddress((void**)&gxc,  g_gxc);
    cudaGetSymbolAddress((void**)&comb, g_comb);
    cudaGetSymbolAddress((void**)&hf,   g_hf);
    cudaGetSymbolAddress((void**)&cf,   g_cf);
    cudaGetSymbolAddress((void**)&hb,   g_hb);
    cudaGetSymbolAddress((void**)&cb,   g_cb);
    cudaGetSymbolAddress((void**)&hc,   g_hc);
    cudaGetSymbolAddress((void**)&cc,   g_cc);

    float* hfb[2] = {hf, hf + BSZ * HID};
    float* hbb[2] = {hb, hb + BSZ * HID};
    float* hcb[2] = {hc, hc + BSZ * H2};

    // initial states (buffer 0)
    cudaMemcpyAsync(hfb[0], h0f, BSZ * HID * sizeof(float), cudaMemcpyDeviceToDevice, 0);
    cudaMemcpyAsync(cf,     c0f, BSZ * HID * sizeof(float), cudaMemcpyDeviceToDevice, 0);
    cudaMemcpyAsync(hbb[0], h0b, BSZ * HID * sizeof(float), cudaMemcpyDeviceToDevice, 0);
    cudaMemcpyAsync(cb,     c0b, BSZ * HID * sizeof(float), cudaMemcpyDeviceToDevice, 0);
    cudaMemcpyAsync(hcb[0], h0c, BSZ * H2  * sizeof(float), cudaMemcpyDeviceToDevice, 0);
    cudaMemcpyAsync(cc,     c0c, BSZ * H2  * sizeof(float), cudaMemcpyDeviceToDevice, 0);

    // embedding gather (raw reshape -> flat)
    {
        int total4 = BSZ * SEQ * (HID / 4);
        embed_kernel<<<(total4 + 255) / 256, 256>>>(x, W_emb, (float4*)seq);
    }

    GemmSet Z = {};

    // Batched input projections for f and b cells
    {
        GemmSet sf = Z; sf.A = seq; sf.W = Wih_f; sf.b0 = bih_f; sf.b1 = bhh_f; sf.C = gxf;
        GemmSet sb = Z; sb.A = seq; sb.W = Wih_b; sb.b0 = bih_b; sb.b1 = bhh_b; sb.C = gxb;
        dim3 grid(H4 / BN, (SEQ * BSZ) / BM, 2);
        gemm_tf32<false><<<grid, 256>>>(sf, sb, SEQ * BSZ, H4, HID, 0);
    }

    // f/b recurrences, fused LSTM epilogue (b consumes reversed input proj)
    for (int t = 0; t < SEQ; ++t) {
        GemmSet rf = Z;
        rf.A = hfb[t & 1]; rf.W = Whh_f; rf.D = gxf + (size_t)t * BSZ * H4;
        rf.cbuf = cf; rf.hout = hfb[(t + 1) & 1];
        rf.comb = comb + (size_t)t * BSZ * H2; rf.combStride = H2;
        GemmSet rb = Z;
        rb.A = hbb[t & 1]; rb.W = Whh_b; rb.D = gxb + (size_t)(SEQ - 1 - t) * BSZ * H4;
        rb.cbuf = cb; rb.hout = hbb[(t + 1) & 1];
        rb.comb = comb + (size_t)t * BSZ * H2 + HID; rb.combStride = H2;
        dim3 grid(HID / 32, BSZ / BM, 2);
        gemm_tf32<true><<<grid, 256>>>(rf, rb, BSZ, 0, HID, HID);
    }

    // Batched input projection for combiner cell
    {
        GemmSet sc = Z; sc.A = comb; sc.W = Wih_c; sc.b0 = bih_c; sc.b1 = bhh_c; sc.C = gxc;
        dim3 grid(H8 / BN, (SEQ * BSZ) / BM, 1);
        gemm_tf32<false><<<grid, 256>>>(sc, sc, SEQ * BSZ, H8, H2, 0);
    }

    // combiner recurrence, fused LSTM epilogue
    for (int t = 0; t < SEQ; ++t) {
        GemmSet rc = Z;
        rc.A = hcb[t & 1]; rc.W = Whh_c; rc.D = gxc + (size_t)t * BSZ * H8;
        rc.cbuf = cc; rc.hout = hcb[(t + 1) & 1];
        dim3 grid(H2 / 32, BSZ / BM, 1);
        gemm_tf32<true><<<grid, 256>>>(rc, rc, BSZ, 0, H2, H2);
    }

    // output head: out = hc_final @ Wout^T + bout  (final h is in buffer 0)
    {
        GemmSet so = Z; so.A = hcb[0]; so.W = Wout; so.b0 = bout; so.C = out;
        dim3 grid(VOC / BN, BSZ / BM, 1);
        gemm_tf32<false><<<grid, 256>>>(so, so, BSZ, VOC, H2, 0);
    }
}

// round 5
// speedup vs baseline: 4.0911x; 1.1143x over previous
#include <cuda_runtime.h>
#include <cuda_bf16.h>
#include <math.h>

// Problem constants
#define BSZ 256
#define SEQ 64
#define HID 512
#define H2  1024
#define H4  2048
#define H8  4096
#define VOC 32000

// ---------------------------------------------------------------------------
// Scratch (no allocations allowed -> __device__ globals)
// ---------------------------------------------------------------------------
__device__ float g_seq   [SEQ * BSZ * HID];
__device__ float g_gxf   [SEQ * BSZ * H4];
__device__ float g_gxb   [SEQ * BSZ * H4];
__device__ float g_gxc   [SEQ * BSZ * H8];
__device__ float g_comb  [SEQ * BSZ * H2];
__device__ float g_hf[2][BSZ * HID];
__device__ float g_cf[BSZ * HID];
__device__ float g_hb[2][BSZ * HID];
__device__ float g_cb[BSZ * HID];
__device__ float g_hc[2][BSZ * H2];
__device__ float g_cc[BSZ * H2];

// ---------------------------------------------------------------------------
// Embedding gather, float4-vectorized.
// ---------------------------------------------------------------------------
__global__ __launch_bounds__(256)
void embed_kernel(const int* __restrict__ x,
                  const float* __restrict__ W,
                  float4* __restrict__ seq)
{
    const int H4v = HID / 4;
    int i = blockIdx.x * blockDim.x + threadIdx.x;
    if (i >= BSZ * SEQ * H4v) return;
    int row = i / H4v;
    int h4  = i - row * H4v;
    int idx = x[row];
    float4 v = make_float4(0.f, 0.f, 0.f, 0.f);
    if (idx != 0)
        v = reinterpret_cast<const float4*>(W)[(size_t)idx * H4v + h4];
    seq[i] = v;
}

// ---------------------------------------------------------------------------
// tf32 tensor-core GEMM, 64x128 block tile, BK=16, 256 threads (8 warps,
// warp tile 32x32). 3-stage cp.async pipeline gmem->smem (fp32 in smem,
// cvt to tf32 in registers after fragment LDS). Smem [row][k] stride 20.
//
// Plain mode  (FUSED=false): C = A(MxK) @ W(NxK)^T [+D] [+b0] [+b1]
// Fused mode  (FUSED=true):  gate-interleaved column mapping; each block
//   covers 32 j-columns x 4 gates; epilogue applies the LSTM cell.
// ---------------------------------------------------------------------------
struct GemmSet {
    const float* A;
    const float* W;
    const float* D;      // plain: optional addend (MxN); fused: gx (B,4*Hd)
    const float* b0;     // plain only
    const float* b1;     // plain only
    float*       C;      // plain only
    float*       cbuf;   // fused: cell state (B,Hd), read+write
    float*       hout;   // fused: next h (B,Hd)
    float*       comb;   // fused: optional (B, combStride) h scatter
    int          combStride;
};

#define BM 64
#define BN 128
#define BKK 16
#define KST 20    // smem k-stride in floats (16 + 4 pad)
#define STG 3     // cp.async pipeline stages

#define CP_ASYNC16(dst, src) \
    asm volatile("cp.async.ca.shared.global [%0], [%1], 16;\n" \
                 :: "r"(dst), "l"(src))
#define CP_COMMIT() asm volatile("cp.async.commit_group;\n" ::: "memory")
#define CP_WAIT(n)  asm volatile("cp.async.wait_group %0;\n" :: "n"(n) : "memory")

__device__ __forceinline__ unsigned f2tf(float f) {
    unsigned r;
    asm("cvt.rna.tf32.f32 %0, %1;" : "=r"(r) : "f"(f));
    return r;
}
__device__ __forceinline__ float sigf(float v) {
    return 1.0f / (1.0f + __expf(-v));
}

template<bool FUSED>
__global__ __launch_bounds__(256)
void gemm_tf32(GemmSet s0, GemmSet s1, int M, int N, int K, int Hd)
{
    GemmSet s = blockIdx.z ? s1 : s0;

    __shared__ float As[STG][BM][KST];
    __shared__ float Bs[STG][BN][KST];

    const int tid  = threadIdx.x;
    const int lane = tid & 31;
    const int wid  = tid >> 5;
    const int wm   = wid & 1;       // 0..1 -> m offset wm*32
    const int wn   = wid >> 1;      // 0..3 -> n offset wn*32
    const int m0   = blockIdx.y * BM;
    const int n0   = blockIdx.x * BN;   // plain column base
    const int n0j  = blockIdx.x * 32;   // fused j base
    const int T    = K / BKK;

    // A loader: 64 rows x 4 float4-chunks = 256; thread -> row=tid>>2, k4=tid&3
    const int a_row = tid >> 2;
    const int a_k4  = tid & 3;
    const float* a_src = s.A + (size_t)(m0 + a_row) * K + a_k4 * 4;
    // B loader: 128 rows x 4 chunks = 512; 2 per thread
    int b_row[2], b_k4[2];
    const float* b_src[2];
#pragma unroll
    for (int p = 0; p < 2; ++p) {
        int idx = tid + 256 * p;
        int row = idx >> 2;
        b_row[p] = row;
        b_k4[p]  = idx & 3;
        int wrow;
        if (FUSED) {
            int wn_r = row >> 5;
            int t    = row & 31;
            int gate = t >> 3;
            int cc   = t & 7;
            int j    = n0j + wn_r * 8 + cc;
            wrow = gate * Hd + j;
        } else {
            wrow = n0 + row;
        }
        b_src[p] = s.W + (size_t)wrow * K + b_k4[p] * 4;
    }

    unsigned a_dst = (unsigned)__cvta_generic_to_shared(&As[0][a_row][a_k4 * 4]);
    unsigned b_dst[2];
    b_dst[0] = (unsigned)__cvta_generic_to_shared(&Bs[0][b_row[0]][b_k4[0] * 4]);
    b_dst[1] = (unsigned)__cvta_generic_to_shared(&Bs[0][b_row[1]][b_k4[1] * 4]);
    const unsigned a_stage = BM * KST * 4;      // bytes per A stage
    const unsigned b_stage = BN * KST * 4;      // bytes per B stage

    auto load_stage = [&](int st, int kt) {
        CP_ASYNC16(a_dst + st * a_stage, a_src + kt * BKK);
        CP_ASYNC16(b_dst[0] + st * b_stage, b_src[0] + kt * BKK);
        CP_ASYNC16(b_dst[1] + st * b_stage, b_src[1] + kt * BKK);
    };

    float acc[2][4][4];
#pragma unroll
    for (int i = 0; i < 2; ++i)
#pragma unroll
        for (int j = 0; j < 4; ++j)
#pragma unroll
            for (int r = 0; r < 4; ++r) acc[i][j][r] = 0.f;

    // prologue: stages 0..STG-2
#pragma unroll
    for (int st = 0; st < STG - 1; ++st) {
        if (st < T) load_stage(st, st);
        CP_COMMIT();
    }

    for (int kt = 0; kt < T; ++kt) {
        CP_WAIT(STG - 2);
        __syncthreads();
        const int buf = kt % STG;
#pragma unroll
        for (int ks = 0; ks < 2; ++ks) {
            const int c = ks * 8 + (lane & 3);
            unsigned a[2][4];
#pragma unroll
            for (int mt = 0; mt < 2; ++mt) {
                int r = wm * 32 + mt * 16 + (lane >> 2);
                a[mt][0] = f2tf(As[buf][r    ][c]);
                a[mt][1] = f2tf(As[buf][r + 8][c]);
                a[mt][2] = f2tf(As[buf][r    ][c + 4]);
                a[mt][3] = f2tf(As[buf][r + 8][c + 4]);
            }
#pragma unroll
            for (int nt = 0; nt < 4; ++nt) {
                int n = wn * 32 + nt * 8 + (lane >> 2);
                unsigned b0 = f2tf(Bs[buf][n][c]);
                unsigned b1 = f2tf(Bs[buf][n][c + 4]);
#pragma unroll
                for (int mt = 0; mt < 2; ++mt) {
                    asm volatile(
                        "mma.sync.aligned.m16n8k8.row.col.f32.tf32.tf32.f32 "
                        "{%0,%1,%2,%3}, {%4,%5,%6,%7}, {%8,%9}, {%0,%1,%2,%3};"
                        : "+f"(acc[mt][nt][0]), "+f"(acc[mt][nt][1]),
                          "+f"(acc[mt][nt][2]), "+f"(acc[mt][nt][3])
                        : "r"(a[mt][0]), "r"(a[mt][1]),
                          "r"(a[mt][2]), "r"(a[mt][3]),
                          "r"(b0), "r"(b1));
                }
            }
        }
        const int nk = kt + STG - 1;
        if (nk < T) load_stage(nk % STG, nk);
        CP_COMMIT();
    }

    if (!FUSED) {
        // Plain epilogue: acc[mt][nt][rr*2+cc] -> C[m + rr*8][n + cc]
#pragma unroll
        for (int mt = 0; mt < 2; ++mt) {
#pragma unroll
            for (int nt = 0; nt < 4; ++nt) {
                int m = m0 + wm * 32 + mt * 16 + (lane >> 2);
                int n = n0 + wn * 32 + nt * 8 + (lane & 3) * 2;
#pragma unroll
                for (int rr = 0; rr < 2; ++rr) {
                    int mm = m + rr * 8;
                    size_t off = (size_t)mm * N + n;
                    float v0 = acc[mt][nt][rr * 2 + 0];
                    float v1 = acc[mt][nt][rr * 2 + 1];
                    if (s.D)  { v0 += s.D[off];  v1 += s.D[off + 1]; }
                    if (s.b0) { v0 += s.b0[n];   v1 += s.b0[n + 1]; }
                    if (s.b1) { v0 += s.b1[n];   v1 += s.b1[n + 1]; }
                    *reinterpret_cast<float2*>(s.C + off) = make_float2(v0, v1);
                }
            }
        }
    } else {
        // Fused LSTM epilogue: nt == gate (i,f,g,o); j pair per thread.
        const int j = n0j + wn * 8 + (lane & 3) * 2;
#pragma unroll
        for (int mt = 0; mt < 2; ++mt) {
#pragma unroll
            for (int rr = 0; rr < 2; ++rr) {
                int m = m0 + wm * 32 + mt * 16 + (lane >> 2) + rr * 8;
                const float* gx = s.D + (size_t)m * 4 * Hd;
                float2 di = *reinterpret_cast<const float2*>(gx +           j);
                float2 df = *reinterpret_cast<const float2*>(gx +     Hd +  j);
                float2 dg = *reinterpret_cast<const float2*>(gx + 2 * Hd +  j);
                float2 do_= *reinterpret_cast<const float2*>(gx + 3 * Hd +  j);
                float2 cv = *reinterpret_cast<const float2*>(
                    s.cbuf + (size_t)m * Hd + j);

                float pi0 = acc[mt][0][rr * 2 + 0] + di.x;
                float pi1 = acc[mt][0][rr * 2 + 1] + di.y;
                float pf0 = acc[mt][1][rr * 2 + 0] + df.x;
                float pf1 = acc[mt][1][rr * 2 + 1] + df.y;
                float pg0 = acc[mt][2][rr * 2 + 0] + dg.x;
                float pg1 = acc[mt][2][rr * 2 + 1] + dg.y;
                float po0 = acc[mt][3][rr * 2 + 0] + do_.x;
                float po1 = acc[mt][3][rr * 2 + 1] + do_.y;

                float cn0 = sigf(pf0) * cv.x + sigf(pi0) * tanhf(pg0);
                float cn1 = sigf(pf1) * cv.y + sigf(pi1) * tanhf(pg1);
                float hn0 = sigf(po0) * tanhf(cn0);
                float hn1 = sigf(po1) * tanhf(cn1);

                *reinterpret_cast<float2*>(s.cbuf + (size_t)m * Hd + j) =
                    make_float2(cn0, cn1);
                *reinterpret_cast<float2*>(s.hout + (size_t)m * Hd + j) =
                    make_float2(hn0, hn1);
                if (s.comb)
                    *reinterpret_cast<float2*>(
                        s.comb + (size_t)m * s.combStride + j) =
                        make_float2(hn0, hn1);
            }
        }
    }
}

// ---------------------------------------------------------------------------
// kernel_launch
// ---------------------------------------------------------------------------
extern "C" void kernel_launch(void* const* d_in, const int* in_sizes, int n_in,
                              void* d_out, int out_size)
{
    const int*   x     = (const int*)  d_in[0];
    const float* W_emb = (const float*)d_in[1];
    const float* Wih_f = (const float*)d_in[2];
    const float* Whh_f = (const float*)d_in[3];
    const float* bih_f = (const float*)d_in[4];
    const float* bhh_f = (const float*)d_in[5];
    const float* Wih_b = (const float*)d_in[6];
    const float* Whh_b = (const float*)d_in[7];
    const float* bih_b = (const float*)d_in[8];
    const float* bhh_b = (const float*)d_in[9];
    const float* Wih_c = (const float*)d_in[10];
    const float* Whh_c = (const float*)d_in[11];
    const float* bih_c = (const float*)d_in[12];
    const float* bhh_c = (const float*)d_in[13];
    const float* Wout  = (const float*)d_in[14];
    const float* bout  = (const float*)d_in[15];
    const float* h0f   = (const float*)d_in[16];
    const float* c0f   = (const float*)d_in[17];
    const float* h0b   = (const float*)d_in[18];
    const float* c0b   = (const float*)d_in[19];
    const float* h0c   = (const float*)d_in[20];
    const float* c0c   = (const float*)d_in[21];
    float* out = (float*)d_out;

    float *seq, *gxf, *gxb, *gxc, *comb;
    float *hf, *cf, *hb, *cb, *hc, *cc;
    cudaGetSymbolAddress((void**)&seq,  g_seq);
    cudaGetSymbolAddress((void**)&gxf,  g_gxf);
    cudaGetSymbolAddress((void**)&gxb,  g_gxb);
    cudaGetSymbolAddress((void**)&gxc,  g_gxc);
    cudaGetSymbolAddress((void**)&comb, g_comb);
    cudaGetSymbolAddress((void**)&hf,   g_hf);
    cudaGetSymbolAddress((void**)&cf,   g_cf);
    cudaGetSymbolAddress((void**)&hb,   g_hb);
    cudaGetSymbolAddress((void**)&cb,   g_cb);
    cudaGetSymbolAddress((void**)&hc,   g_hc);
    cudaGetSymbolAddress((void**)&cc,   g_cc);

    float* hfb[2] = {hf, hf + BSZ * HID};
    float* hbb[2] = {hb, hb + BSZ * HID};
    float* hcb[2] = {hc, hc + BSZ * H2};

    // initial states (buffer 0)
    cudaMemcpyAsync(hfb[0], h0f, BSZ * HID * sizeof(float), cudaMemcpyDeviceToDevice, 0);
    cudaMemcpyAsync(cf,     c0f, BSZ * HID * sizeof(float), cudaMemcpyDeviceToDevice, 0);
    cudaMemcpyAsync(hbb[0], h0b, BSZ * HID * sizeof(float), cudaMemcpyDeviceToDevice, 0);
    cudaMemcpyAsync(cb,     c0b, BSZ * HID * sizeof(float), cudaMemcpyDeviceToDevice, 0);
    cudaMemcpyAsync(hcb[0], h0c, BSZ * H2  * sizeof(float), cudaMemcpyDeviceToDevice, 0);
    cudaMemcpyAsync(cc,     c0c, BSZ * H2  * sizeof(float), cudaMemcpyDeviceToDevice, 0);

    // embedding gather (raw reshape -> flat)
    {
        int total4 = BSZ * SEQ * (HID / 4);
        embed_kernel<<<(total4 + 255) / 256, 256>>>(x, W_emb, (float4*)seq);
    }

    GemmSet Z = {};

    // Batched input projections for f and b cells
    {
        GemmSet sf = Z; sf.A = seq; sf.W = Wih_f; sf.b0 = bih_f; sf.b1 = bhh_f; sf.C = gxf;
        GemmSet sb = Z; sb.A = seq; sb.W = Wih_b; sb.b0 = bih_b; sb.b1 = bhh_b; sb.C = gxb;
        dim3 grid(H4 / BN, (SEQ * BSZ) / BM, 2);
        gemm_tf32<false><<<grid, 256>>>(sf, sb, SEQ * BSZ, H4, HID, 0);
    }

    // f/b recurrences, fused LSTM epilogue (b consumes reversed input proj)
    for (int t = 0; t < SEQ; ++t) {
        GemmSet rf = Z;
        rf.A = hfb[t & 1]; rf.W = Whh_f; rf.D = gxf + (size_t)t * BSZ * H4;
        rf.cbuf = cf; rf.hout = hfb[(t + 1) & 1];
        rf.comb = comb + (size_t)t * BSZ * H2; rf.combStride = H2;
        GemmSet rb = Z;
        rb.A = hbb[t & 1]; rb.W = Whh_b; rb.D = gxb + (size_t)(SEQ - 1 - t) * BSZ * H4;
        rb.cbuf = cb; rb.hout = hbb[(t + 1) & 1];
        rb.comb = comb + (size_t)t * BSZ * H2 + HID; rb.combStride = H2;
        dim3 grid(HID / 32, BSZ / BM, 2);
        gemm_tf32<true><<<grid, 256>>>(rf, rb, BSZ, 0, HID, HID);
    }

    // Batched input projection for combiner cell
    {
        GemmSet sc = Z; sc.A = comb; sc.W = Wih_c; sc.b0 = bih_c; sc.b1 = bhh_c; sc.C = gxc;
        dim3 grid(H8 / BN, (SEQ * BSZ) / BM, 1);
        gemm_tf32<false><<<grid, 256>>>(sc, sc, SEQ * BSZ, H8, H2, 0);
    }

    // combiner recurrence, fused LSTM epilogue
    for (int t = 0; t < SEQ; ++t) {
        GemmSet rc = Z;
        rc.A = hcb[t & 1]; rc.W = Whh_c; rc.D = gxc + (size_t)t * BSZ * H8;
        rc.cbuf = cc; rc.hout = hcb[(t + 1) & 1];
        dim3 grid(H2 / 32, BSZ / BM, 1);
        gemm_tf32<true><<<grid, 256>>>(rc, rc, BSZ, 0, H2, H2);
    }

    // output head: out = hc_final @ Wout^T + bout  (final h is in buffer 0)
    {
        GemmSet so = Z; so.A = hcb[0]; so.W = Wout; so.b0 = bout; so.C = out;
        dim3 grid(VOC / BN, BSZ / BM, 1);
        gemm_tf32<false><<<grid, 256>>>(so, so, BSZ, VOC, H2, 0);
    }
}

// round 6
// speedup vs baseline: 7.3327x; 1.7923x over previous
#include <cuda_runtime.h>
#include <cuda_fp16.h>
#include <math.h>

// Problem constants
#define BSZ 256
#define SEQ 64
#define HID 512
#define H2  1024
#define H4  2048
#define H8  4096
#define VOC 32000

// ---------------------------------------------------------------------------
// Scratch (no allocations allowed -> __device__ globals)
// ---------------------------------------------------------------------------
__device__ __half g_seq [SEQ * BSZ * HID];     // fp16 embedded sequence
__device__ float  g_gxf [SEQ * BSZ * H4];      // fp32 input projections
__device__ float  g_gxb [SEQ * BSZ * H4];
__device__ float  g_gxc [SEQ * BSZ * H8];
__device__ __half g_comb[SEQ * BSZ * H2];      // fp16 concat(hf, hb)
__device__ __half g_hf[2][BSZ * HID];
__device__ float  g_cf[BSZ * HID];
__device__ __half g_hb[2][BSZ * HID];
__device__ float  g_cb[BSZ * HID];
__device__ __half g_hc[2][BSZ * H2];
__device__ float  g_cc[BSZ * H2];
// fp16 weight copies (converted once per launch)
__device__ __half g_wihf[H4 * HID];
__device__ __half g_whhf[H4 * HID];
__device__ __half g_wihb[H4 * HID];
__device__ __half g_whhb[H4 * HID];
__device__ __half g_wihc[H8 * H2];
__device__ __half g_whhc[H8 * H2];
__device__ __half g_wout[VOC * H2];

// ---------------------------------------------------------------------------
// fp32 -> fp16 conversion (4 elems/thread)
// ---------------------------------------------------------------------------
struct __align__(8) Half4 { __half2 a, b; };

__global__ __launch_bounds__(256)
void cvt_kernel(const float4* __restrict__ in, Half4* __restrict__ out, int n4)
{
    int i = blockIdx.x * blockDim.x + threadIdx.x;
    if (i >= n4) return;
    float4 v = in[i];
    Half4 h;
    h.a = __floats2half2_rn(v.x, v.y);
    h.b = __floats2half2_rn(v.z, v.w);
    out[i] = h;
}

// ---------------------------------------------------------------------------
// Embedding gather -> fp16, 4 elems/thread.
// ---------------------------------------------------------------------------
__global__ __launch_bounds__(256)
void embed_kernel(const int* __restrict__ x,
                  const float* __restrict__ W,
                  Half4* __restrict__ seq)
{
    const int H4v = HID / 4;
    int i = blockIdx.x * blockDim.x + threadIdx.x;
    if (i >= BSZ * SEQ * H4v) return;
    int row = i / H4v;
    int h4  = i - row * H4v;
    int idx = x[row];
    float4 v = make_float4(0.f, 0.f, 0.f, 0.f);
    if (idx != 0)
        v = reinterpret_cast<const float4*>(W)[(size_t)idx * H4v + h4];
    Half4 h;
    h.a = __floats2half2_rn(v.x, v.y);
    h.b = __floats2half2_rn(v.z, v.w);
    seq[i] = h;
}

// ---------------------------------------------------------------------------
// fp16 tensor-core GEMM, 64x128 block tile, BK=32 (halves), 256 threads
// (8 warps, warp tile 32x32), mma.m16n8k16.f32.f16.f16.f32, ldmatrix A,
// 3-stage cp.async pipeline. Smem [row][k] stride 40 halves (bank-free).
//
// Plain mode  (FUSED=false): C(f32) = A(MxK,f16) @ W(NxK,f16)^T [+b0] [+b1]
// Fused mode  (FUSED=true):  gate-interleaved columns; LSTM epilogue with
//   fp32 gx addend + fp32 cell state; writes h (fp16) and optional comb.
// ---------------------------------------------------------------------------
struct GemmSet {
    const __half* A;
    const __half* W;
    const float*  D;     // plain: unused; fused: gx (B, 4*Hd) fp32
    const float*  b0;    // plain only
    const float*  b1;    // plain only
    float*        C;     // plain only (fp32 out)
    float*        cbuf;  // fused: cell state fp32, read+write
    __half*       hout;  // fused: next h fp16
    __half*       comb;  // fused: optional fp16 h scatter
    int           combStride;
};

#define BM 64
#define BN 128
#define BKH 32    // k per tile, in halves
#define KSTH 40   // smem k-stride in halves (32 + 8 pad)
#define STG 3

#define CP_ASYNC16(dst, src) \
    asm volatile("cp.async.ca.shared.global [%0], [%1], 16;\n" \
                 :: "r"(dst), "l"(src))
#define CP_COMMIT() asm volatile("cp.async.commit_group;\n" ::: "memory")
#define CP_WAIT(n)  asm volatile("cp.async.wait_group %0;\n" :: "n"(n) : "memory")

__device__ __forceinline__ void ldsm4(unsigned& r0, unsigned& r1,
                                      unsigned& r2, unsigned& r3,
                                      unsigned addr)
{
    asm volatile("ldmatrix.sync.aligned.m8n8.x4.shared.b16 {%0,%1,%2,%3}, [%4];"
                 : "=r"(r0), "=r"(r1), "=r"(r2), "=r"(r3) : "r"(addr));
}
__device__ __forceinline__ float sigf(float v) {
    return 1.0f / (1.0f + __expf(-v));
}

template<bool FUSED>
__global__ __launch_bounds__(256)
void gemm_f16(GemmSet s0, GemmSet s1, int M, int N, int K, int Hd)
{
    GemmSet s = blockIdx.z ? s1 : s0;

    __shared__ __half As[STG][BM][KSTH];   // 15360 B
    __shared__ __half Bs[STG][BN][KSTH];   // 30720 B

    const int tid  = threadIdx.x;
    const int lane = tid & 31;
    const int wid  = tid >> 5;
    const int wm   = wid & 1;        // m offset wm*32
    const int wn   = wid >> 1;       // n offset wn*32
    const int m0   = blockIdx.y * BM;
    const int n0   = blockIdx.x * BN;    // plain column base
    const int n0j  = blockIdx.x * 32;    // fused j base
    const int T    = K / BKH;

    // A loader: 64 rows x 4 granules (8 halves = 16B each)
    const int a_row = tid >> 2;
    const int a_g   = tid & 3;
    const __half* a_src = s.A + (size_t)(m0 + a_row) * K + a_g * 8;
    // B loader: 128 rows x 4 granules, 2 per thread
    int b_row[2], b_g[2];
    const __half* b_src[2];
#pragma unroll
    for (int p = 0; p < 2; ++p) {
        int idx = tid + 256 * p;
        int row = idx >> 2;
        b_row[p] = row;
        b_g[p]   = idx & 3;
        int wrow;
        if (FUSED) {
            int wn_r = row >> 5;
            int t    = row & 31;
            int gate = t >> 3;
            int cc   = t & 7;
            int j    = n0j + wn_r * 8 + cc;
            wrow = gate * Hd + j;
        } else {
            wrow = n0 + row;
        }
        b_src[p] = s.W + (size_t)wrow * K + b_g[p] * 8;
    }

    unsigned a_dst = (unsigned)__cvta_generic_to_shared(&As[0][a_row][a_g * 8]);
    unsigned b_dst[2];
    b_dst[0] = (unsigned)__cvta_generic_to_shared(&Bs[0][b_row[0]][b_g[0] * 8]);
    b_dst[1] = (unsigned)__cvta_generic_to_shared(&Bs[0][b_row[1]][b_g[1] * 8]);
    const unsigned a_stage = BM * KSTH * 2;
    const unsigned b_stage = BN * KSTH * 2;

    auto load_stage = [&](int st, int kt) {
        CP_ASYNC16(a_dst + st * a_stage, a_src + kt * BKH);
        CP_ASYNC16(b_dst[0] + st * b_stage, b_src[0] + kt * BKH);
        CP_ASYNC16(b_dst[1] + st * b_stage, b_src[1] + kt * BKH);
    };

    // smem bases for fragment loads
    const unsigned as_base = (unsigned)__cvta_generic_to_shared(&As[0][0][0]);

    float acc[2][4][4];
#pragma unroll
    for (int i = 0; i < 2; ++i)
#pragma unroll
        for (int j = 0; j < 4; ++j)
#pragma unroll
            for (int r = 0; r < 4; ++r) acc[i][j][r] = 0.f;

    // prologue
#pragma unroll
    for (int st = 0; st < STG - 1; ++st) {
        if (st < T) load_stage(st, st);
        CP_COMMIT();
    }

    // ldmatrix lane addressing (constant per thread)
    const int lm_row = lane & 15;              // row within 16
    const int lm_k   = (lane >> 4) << 3;       // 0 or 8

    for (int kt = 0; kt < T; ++kt) {
        CP_WAIT(STG - 2);
        __syncthreads();
        const int buf = kt % STG;
#pragma unroll
        for (int ks = 0; ks < 2; ++ks) {
            const int c = ks * 16;             // k16 base within tile
            unsigned a[2][4];
#pragma unroll
            for (int mt = 0; mt < 2; ++mt) {
                int r0 = wm * 32 + mt * 16;
                unsigned addr = as_base +
                    ((unsigned)buf * a_stage) +
                    ((r0 + lm_row) * KSTH + c + lm_k) * 2;
                ldsm4(a[mt][0], a[mt][1], a[mt][2], a[mt][3], addr);
            }
#pragma unroll
            for (int nt = 0; nt < 4; ++nt) {
                int n = wn * 32 + nt * 8 + (lane >> 2);
                unsigned b0 = *reinterpret_cast<const unsigned*>(
                    &Bs[buf][n][c + (lane & 3) * 2]);
                unsigned b1 = *reinterpret_cast<const unsigned*>(
                    &Bs[buf][n][c + 8 + (lane & 3) * 2]);
#pragma unroll
                for (int mt = 0; mt < 2; ++mt) {
                    asm volatile(
                        "mma.sync.aligned.m16n8k16.row.col.f32.f16.f16.f32 "
                        "{%0,%1,%2,%3}, {%4,%5,%6,%7}, {%8,%9}, {%0,%1,%2,%3};"
                        : "+f"(acc[mt][nt][0]), "+f"(acc[mt][nt][1]),
                          "+f"(acc[mt][nt][2]), "+f"(acc[mt][nt][3])
                        : "r"(a[mt][0]), "r"(a[mt][1]),
                          "r"(a[mt][2]), "r"(a[mt][3]),
                          "r"(b0), "r"(b1));
                }
            }
        }
        const int nk = kt + STG - 1;
        if (nk < T) load_stage(nk % STG, nk);
        CP_COMMIT();
    }

    if (!FUSED) {
        // Plain epilogue -> fp32 C
#pragma unroll
        for (int mt = 0; mt < 2; ++mt) {
#pragma unroll
            for (int nt = 0; nt < 4; ++nt) {
                int m = m0 + wm * 32 + mt * 16 + (lane >> 2);
                int n = n0 + wn * 32 + nt * 8 + (lane & 3) * 2;
#pragma unroll
                for (int rr = 0; rr < 2; ++rr) {
                    int mm = m + rr * 8;
                    size_t off = (size_t)mm * N + n;
                    float v0 = acc[mt][nt][rr * 2 + 0];
                    float v1 = acc[mt][nt][rr * 2 + 1];
                    if (s.b0) { v0 += s.b0[n]; v1 += s.b0[n + 1]; }
                    if (s.b1) { v0 += s.b1[n]; v1 += s.b1[n + 1]; }
                    *reinterpret_cast<float2*>(s.C + off) = make_float2(v0, v1);
                }
            }
        }
    } else {
        // Fused LSTM epilogue: nt == gate (i,f,g,o); j pair per thread.
        const int j = n0j + wn * 8 + (lane & 3) * 2;
#pragma unroll
        for (int mt = 0; mt < 2; ++mt) {
#pragma unroll
            for (int rr = 0; rr < 2; ++rr) {
                int m = m0 + wm * 32 + mt * 16 + (lane >> 2) + rr * 8;
                const float* gx = s.D + (size_t)m * 4 * Hd;
                float2 di = *reinterpret_cast<const float2*>(gx +          j);
                float2 df = *reinterpret_cast<const float2*>(gx +     Hd + j);
                float2 dg = *reinterpret_cast<const float2*>(gx + 2 * Hd + j);
                float2 do_= *reinterpret_cast<const float2*>(gx + 3 * Hd + j);
                float2 cv = *reinterpret_cast<const float2*>(
                    s.cbuf + (size_t)m * Hd + j);

                float pi0 = acc[mt][0][rr * 2 + 0] + di.x;
                float pi1 = acc[mt][0][rr * 2 + 1] + di.y;
                float pf0 = acc[mt][1][rr * 2 + 0] + df.x;
                float pf1 = acc[mt][1][rr * 2 + 1] + df.y;
                float pg0 = acc[mt][2][rr * 2 + 0] + dg.x;
                float pg1 = acc[mt][2][rr * 2 + 1] + dg.y;
                float po0 = acc[mt][3][rr * 2 + 0] + do_.x;
                float po1 = acc[mt][3][rr * 2 + 1] + do_.y;

                float cn0 = sigf(pf0) * cv.x + sigf(pi0) * tanhf(pg0);
                float cn1 = sigf(pf1) * cv.y + sigf(pi1) * tanhf(pg1);
                float hn0 = sigf(po0) * tanhf(cn0);
                float hn1 = sigf(po1) * tanhf(cn1);

                *reinterpret_cast<float2*>(s.cbuf + (size_t)m * Hd + j) =
                    make_float2(cn0, cn1);
                __half2 hh = __floats2half2_rn(hn0, hn1);
                *reinterpret_cast<__half2*>(s.hout + (size_t)m * Hd + j) = hh;
                if (s.comb)
                    *reinterpret_cast<__half2*>(
                        s.comb + (size_t)m * s.combStride + j) = hh;
            }
        }
    }
}

// ---------------------------------------------------------------------------
// kernel_launch
// ---------------------------------------------------------------------------
extern "C" void kernel_launch(void* const* d_in, const int* in_sizes, int n_in,
                              void* d_out, int out_size)
{
    const int*   x     = (const int*)  d_in[0];
    const float* W_emb = (const float*)d_in[1];
    const float* Wih_f = (const float*)d_in[2];
    const float* Whh_f = (const float*)d_in[3];
    const float* bih_f = (const float*)d_in[4];
    const float* bhh_f = (const float*)d_in[5];
    const float* Wih_b = (const float*)d_in[6];
    const float* Whh_b = (const float*)d_in[7];
    const float* bih_b = (const float*)d_in[8];
    const float* bhh_b = (const float*)d_in[9];
    const float* Wih_c = (const float*)d_in[10];
    const float* Whh_c = (const float*)d_in[11];
    const float* bih_c = (const float*)d_in[12];
    const float* bhh_c = (const float*)d_in[13];
    const float* Wout  = (const float*)d_in[14];
    const float* bout  = (const float*)d_in[15];
    const float* h0f   = (const float*)d_in[16];
    const float* c0f   = (const float*)d_in[17];
    const float* h0b   = (const float*)d_in[18];
    const float* c0b   = (const float*)d_in[19];
    const float* h0c   = (const float*)d_in[20];
    const float* c0c   = (const float*)d_in[21];
    float* out = (float*)d_out;

    __half *seq, *comb, *hf, *hb, *hc;
    __half *wihf, *whhf, *wihb, *whhb, *wihc, *whhc, *wout;
    float *gxf, *gxb, *gxc, *cf, *cb, *cc;
    cudaGetSymbolAddress((void**)&seq,  g_seq);
    cudaGetSymbolAddress((void**)&gxf,  g_gxf);
    cudaGetSymbolAddress((void**)&gxb,  g_gxb);
    cudaGetSymbolAddress((void**)&gxc,  g_gxc);
    cudaGetSymbolAddress((void**)&comb, g_comb);
    cudaGetSymbolAddress((void**)&hf,   g_hf);
    cudaGetSymbolAddress((void**)&cf,   g_cf);
    cudaGetSymbolAddress((void**)&hb,   g_hb);
    cudaGetSymbolAddress((void**)&cb,   g_cb);
    cudaGetSymbolAddress((void**)&hc,   g_hc);
    cudaGetSymbolAddress((void**)&cc,   g_cc);
    cudaGetSymbolAddress((void**)&wihf, g_wihf);
    cudaGetSymbolAddress((void**)&whhf, g_whhf);
    cudaGetSymbolAddress((void**)&wihb, g_wihb);
    cudaGetSymbolAddress((void**)&whhb, g_whhb);
    cudaGetSymbolAddress((void**)&wihc, g_wihc);
    cudaGetSymbolAddress((void**)&whhc, g_whhc);
    cudaGetSymbolAddress((void**)&wout, g_wout);

    __half* hfb[2] = {hf, hf + BSZ * HID};
    __half* hbb[2] = {hb, hb + BSZ * HID};
    __half* hcb[2] = {hc, hc + BSZ * H2};

    auto cvt = [](const float* in, __half* out_, int n) {
        int n4 = n / 4;
        cvt_kernel<<<(n4 + 255) / 256, 256>>>(
            (const float4*)in, (Half4*)out_, n4);
    };

    // weight + initial-state conversions (fp32 -> fp16)
    cvt(Wih_f, wihf, H4 * HID);
    cvt(Whh_f, whhf, H4 * HID);
    cvt(Wih_b, wihb, H4 * HID);
    cvt(Whh_b, whhb, H4 * HID);
    cvt(Wih_c, wihc, H8 * H2);
    cvt(Whh_c, whhc, H8 * H2);
    cvt(Wout,  wout, VOC * H2);
    cvt(h0f, hfb[0], BSZ * HID);
    cvt(h0b, hbb[0], BSZ * HID);
    cvt(h0c, hcb[0], BSZ * H2);

    // fp32 cell states
    cudaMemcpyAsync(cf, c0f, BSZ * HID * sizeof(float), cudaMemcpyDeviceToDevice, 0);
    cudaMemcpyAsync(cb, c0b, BSZ * HID * sizeof(float), cudaMemcpyDeviceToDevice, 0);
    cudaMemcpyAsync(cc, c0c, BSZ * H2  * sizeof(float), cudaMemcpyDeviceToDevice, 0);

    // embedding gather (raw reshape -> flat), fp16 output
    {
        int total4 = BSZ * SEQ * (HID / 4);
        embed_kernel<<<(total4 + 255) / 256, 256>>>(x, W_emb, (Half4*)seq);
    }

    GemmSet Z = {};

    // Batched input projections for f and b cells (fp32 out)
    {
        GemmSet sf = Z; sf.A = seq; sf.W = wihf; sf.b0 = bih_f; sf.b1 = bhh_f; sf.C = gxf;
        GemmSet sb = Z; sb.A = seq; sb.W = wihb; sb.b0 = bih_b; sb.b1 = bhh_b; sb.C = gxb;
        dim3 grid(H4 / BN, (SEQ * BSZ) / BM, 2);
        gemm_f16<false><<<grid, 256>>>(sf, sb, SEQ * BSZ, H4, HID, 0);
    }

    // f/b recurrences, fused LSTM epilogue (b consumes reversed input proj)
    for (int t = 0; t < SEQ; ++t) {
        GemmSet rf = Z;
        rf.A = hfb[t & 1]; rf.W = whhf; rf.D = gxf + (size_t)t * BSZ * H4;
        rf.cbuf = cf; rf.hout = hfb[(t + 1) & 1];
        rf.comb = comb + (size_t)t * BSZ * H2; rf.combStride = H2;
        GemmSet rb = Z;
        rb.A = hbb[t & 1]; rb.W = whhb; rb.D = gxb + (size_t)(SEQ - 1 - t) * BSZ * H4;
        rb.cbuf = cb; rb.hout = hbb[(t + 1) & 1];
        rb.comb = comb + (size_t)t * BSZ * H2 + HID; rb.combStride = H2;
        dim3 grid(HID / 32, BSZ / BM, 2);
        gemm_f16<true><<<grid, 256>>>(rf, rb, BSZ, 0, HID, HID);
    }

    // Batched input projection for combiner cell
    {
        GemmSet sc = Z; sc.A = comb; sc.W = wihc; sc.b0 = bih_c; sc.b1 = bhh_c; sc.C = gxc;
        dim3 grid(H8 / BN, (SEQ * BSZ) / BM, 1);
        gemm_f16<false><<<grid, 256>>>(sc, sc, SEQ * BSZ, H8, H2, 0);
    }

    // combiner recurrence, fused LSTM epilogue
    for (int t = 0; t < SEQ; ++t) {
        GemmSet rc = Z;
        rc.A = hcb[t & 1]; rc.W = whhc; rc.D = gxc + (size_t)t * BSZ * H8;
        rc.cbuf = cc; rc.hout = hcb[(t + 1) & 1];
        dim3 grid(H2 / 32, BSZ / BM, 1);
        gemm_f16<true><<<grid, 256>>>(rc, rc, BSZ, 0, H2, H2);
    }

    // output head: out = hc_final @ Wout^T + bout (final h in buffer 0)
    {
        GemmSet so = Z; so.A = hcb[0]; so.W = wout; so.b0 = bout; so.C = out;
        dim3 grid(VOC / BN, BSZ / BM, 1);
        gemm_f16<false><<<grid, 256>>>(so, so, BSZ, VOC, H2, 0);
    }
}